// round 8
// baseline (speedup 1.0000x reference)
#include <cuda_runtime.h>

#define SEQ 2048
#define BB  64
#define IND 512
#define HH  512
#define NCTA 128
#define NTHR 256

typedef unsigned long long ull;

// ---------------- global scratch (static device memory: allowed) ----------------
// gx layout: [t][group(8)][cta(16)] blocks of 8 rows x 96 cols
// (cols 0-31 z-pre, 32-63 r-pre, 64-95 cand-pre), biases folded. Block = 768 floats.
__device__ float g_gx[(size_t)SEQ * 8 * 16 * 768];
__device__ float g_h[2 * BB * HH];    // ping-pong hidden state (buf = t&1)
__device__ float g_rh[BB * HH];       // r * h_prev (single buffer, safe by protocol)
// flags: [0..255] = flagA (phase1 done), [256..511] = flagB (phase2 done);
// per group 32 u32 (128B line), flag[g*32 + cid] = completed epoch.
__device__ unsigned g_flag[512];

// ---------------- helpers ----------------
__device__ __forceinline__ ull ffma2(ull a, ull b, ull c) {
    ull d;
    asm("fma.rn.f32x2 %0, %1, %2, %3;" : "=l"(d) : "l"(a), "l"(b), "l"(c));
    return d;
}
__device__ __forceinline__ float ull_sum(ull v) {
    return __uint_as_float((unsigned)(v & 0xffffffffULL)) +
           __uint_as_float((unsigned)(v >> 32));
}
__device__ __forceinline__ float sigmoidf_(float x) {
    return 1.0f / (1.0f + __expf(-x));
}
__device__ __forceinline__ float tanhf_(float x) {
    return 1.0f - 2.0f / (__expf(2.0f * x) + 1.0f);
}
// Wait until both flags in the 8B pair reach goal (lane 0 polls, warp syncs after).
__device__ __forceinline__ void wait_pair(const unsigned* fp, unsigned goal) {
    if ((threadIdx.x & 31) == 0) {
        unsigned lo, hi;
        do {
            ull v;
            asm volatile("ld.acquire.gpu.u64 %0, [%1];" : "=l"(v) : "l"(fp) : "memory");
            lo = (unsigned)v; hi = (unsigned)(v >> 32);
        } while (lo < goal || hi < goal);
    }
    __syncwarp();
}
__device__ __forceinline__ void flag_set(unsigned* fp, unsigned val) {
    asm volatile("st.release.gpu.u32 [%0], %1;" :: "l"(fp), "r"(val) : "memory");
}

// ---------------- precompute: gx = x @ [Wg_x | Wc_x] + [bg | bc], remapped ----
__global__ void __launch_bounds__(NTHR) precompute_kernel(
    const float* __restrict__ x, const float* __restrict__ Wg,
    const float* __restrict__ bg, const float* __restrict__ Wc,
    const float* __restrict__ bc, const float* __restrict__ h0)
{
    __shared__ float2 as2[8 * 128];
    __shared__ float2 bs2[8 * 64];

    const int tid = threadIdx.x;

    if (blockIdx.x == 0 && blockIdx.y == 0) {
        for (int i = tid; i < BB * HH; i += NTHR) g_h[i] = h0[i];
        g_flag[tid] = 0u;
        g_flag[tid + 256] = 0u;
    }

    const int bx = blockIdx.x;          // 0..11 (8 Wg tiles, 4 Wc tiles)
    const int m0 = blockIdx.y * 128;

    const float* Wp; const float* bias; int ldw, n0;
    if (bx < 8) { Wp = Wg; bias = bg; ldw = 1024; n0 = bx * 128; }
    else        { Wp = Wc; bias = bc; ldw = 512;  n0 = (bx - 8) * 128; }

    const int tx = tid & 15, ty = tid >> 4;
    const int arow = tid >> 1, acol = (tid & 1) * 4;
    const int bkrow = tid >> 5, bcol2 = (tid & 31) * 2;

    const float* aptr = x + (size_t)(m0 + arow) * IND + acol;
    const float* bptr = Wp + (size_t)bkrow * ldw + n0 + bcol2 * 2;

    float4 areg = *(const float4*)aptr;
    float4 breg = *(const float4*)bptr;

    ull acc[8][4];
#pragma unroll
    for (int i = 0; i < 8; ++i)
#pragma unroll
        for (int j = 0; j < 4; ++j) acc[i][j] = 0ULL;

    for (int kt = 0; kt < IND / 8; ++kt) {
        as2[(acol + 0) * 128 + arow] = make_float2(areg.x, areg.x);
        as2[(acol + 1) * 128 + arow] = make_float2(areg.y, areg.y);
        as2[(acol + 2) * 128 + arow] = make_float2(areg.z, areg.z);
        as2[(acol + 3) * 128 + arow] = make_float2(areg.w, areg.w);
        *(float4*)&bs2[bkrow * 64 + bcol2] = breg;
        __syncthreads();
        if (kt + 1 < IND / 8) {
            areg = *(const float4*)(aptr + (kt + 1) * 8);
            breg = *(const float4*)(bptr + (size_t)(kt + 1) * 8 * ldw);
        }
#pragma unroll
        for (int k = 0; k < 8; ++k) {
            ulonglong2 a01 = *(const ulonglong2*)&as2[k * 128 + ty * 8];
            ulonglong2 a23 = *(const ulonglong2*)&as2[k * 128 + ty * 8 + 2];
            ulonglong2 a45 = *(const ulonglong2*)&as2[k * 128 + ty * 8 + 4];
            ulonglong2 a67 = *(const ulonglong2*)&as2[k * 128 + ty * 8 + 6];
            ulonglong2 b01 = *(const ulonglong2*)&bs2[k * 64 + tx * 4];
            ulonglong2 b23 = *(const ulonglong2*)&bs2[k * 64 + tx * 4 + 2];
            ull av[8] = {a01.x, a01.y, a23.x, a23.y, a45.x, a45.y, a67.x, a67.y};
            ull bv[4] = {b01.x, b01.y, b23.x, b23.y};
#pragma unroll
            for (int i = 0; i < 8; ++i)
#pragma unroll
                for (int j = 0; j < 4; ++j)
                    acc[i][j] = ffma2(av[i], bv[j], acc[i][j]);
        }
        __syncthreads();
    }

    float bvl[8];
#pragma unroll
    for (int j = 0; j < 8; ++j) bvl[j] = bias[n0 + tx * 8 + j];

    // Destination remap: (bx, tx) -> (cta, slot)
    int cta, slot;
    if (bx < 8) {
        int gcol = bx * 128 + tx * 8;
        if (gcol < 512) { cta = gcol >> 5; slot = gcol & 31; }
        else { int rc = gcol - 512; cta = rc >> 5; slot = 32 + (rc & 31); }
    } else {
        int ccol = (bx - 8) * 128 + tx * 8;
        cta = ccol >> 5; slot = 64 + (ccol & 31);
    }

#pragma unroll
    for (int i = 0; i < 8; ++i) {
        int m = m0 + ty * 8 + i;
        int t = m >> 6, b = m & 63, g = b >> 3, r = b & 7;
        float* op = g_gx + (((size_t)t * 8 + g) * 16 + cta) * 768 + r * 96 + slot;
        float2 c0, c1, c2, c3;
        c0.x = __uint_as_float((unsigned)acc[i][0]); c0.y = __uint_as_float((unsigned)(acc[i][0] >> 32));
        c1.x = __uint_as_float((unsigned)acc[i][1]); c1.y = __uint_as_float((unsigned)(acc[i][1] >> 32));
        c2.x = __uint_as_float((unsigned)acc[i][2]); c2.y = __uint_as_float((unsigned)(acc[i][2] >> 32));
        c3.x = __uint_as_float((unsigned)acc[i][3]); c3.y = __uint_as_float((unsigned)(acc[i][3] >> 32));
        *(float4*)(op)     = make_float4(c0.x + bvl[0], c0.y + bvl[1],
                                         c1.x + bvl[2], c1.y + bvl[3]);
        *(float4*)(op + 4) = make_float4(c2.x + bvl[4], c2.y + bvl[5],
                                         c3.x + bvl[6], c3.y + bvl[7]);
    }
}

// ---------------- persistent scan kernel ----------------
// 128 CTAs x 256 thr, 1/SM. Group g = bid>>4 owns batch rows [g*8, g*8+8).
// cid = bid&15: z cols [cid*32,+32), r cols [512+cid*32,+32), cand cols [cid*32,+32).
// Sync: per-CTA epoch flags; warp ks depends only on producer CTAs 2ks, 2ks+1.
// smem: wg 32768 | wc 16384 | hst 4096 (h, then rh) | P 4096 | zb 256 = 230400 B.
#define SM_WG  0
#define SM_WC  32768
#define SM_HST 49152
#define SM_P   53248
#define SM_Z   57344
#define SMEM_FLOATS 57600
#define SMEM_BYTES (SMEM_FLOATS * 4)

__global__ void __launch_bounds__(NTHR, 1) scan_kernel(
    const float* __restrict__ Wg, const float* __restrict__ Wc,
    float* __restrict__ out, int write_outputs, int write_hlast)
{
    extern __shared__ float sm[];
    float* wg  = sm + SM_WG;
    float* wc  = sm + SM_WC;
    float* hst = sm + SM_HST;
    float* P   = sm + SM_P;
    float* zb  = sm + SM_Z;

    const int tid = threadIdx.x;
    const int g   = blockIdx.x >> 4;
    const int cid = blockIdx.x & 15;
    const int r0  = g * 8;
    const int c32 = cid * 32;

    // ---- load recurrent weight slabs once (swizzled, k-contiguous per col) ----
    for (int idx = tid; idx < 64 * 512; idx += NTHR) {
        int k = idx >> 6, c = idx & 63;
        int gc = (c < 32) ? (c32 + c) : (512 + c32 + (c - 32));
        float v = Wg[(size_t)(512 + k) * 1024 + gc];
        wg[c * 512 + (((k >> 2) ^ ((c >> 2) & 7)) << 2) + (k & 3)] = v;
    }
    for (int idx = tid; idx < 32 * 512; idx += NTHR) {
        int k = idx >> 5, c = idx & 31;
        float v = Wc[(size_t)(512 + k) * 512 + c32 + c];
        wc[c * 512 + (((k >> 2) ^ ((c >> 2) & 7)) << 2) + (k & 3)] = v;
    }
    __syncthreads();

    // phase1 mapping: warp ks = k-slice (64 k), lane = (rg:2) x (cg:16), tile 4x4
    const int ks = tid >> 5;
    const int ln = tid & 31;
    const int rg = ln >> 4, cg = ln & 15;
    // phase2 mapping: lane = (rg2:4) x (cg2:8), tile 2x4
    const int rg2 = ln >> 3, cg2 = ln & 7;

    // phase1 epilogue outputs (2 per thread)
    int row1[2], col1[2];
#pragma unroll
    for (int vv = 0; vv < 2; ++vv) {
        int v = ks + 8 * vv;
        row1[vv] = rg * 4 + (v >> 2);
        col1[vv] = cg * 4 + (v & 3);
    }
    // phase2 epilogue output (1 per thread)
    const int v2   = ks;
    const int row2 = rg2 * 2 + (v2 >> 2);
    const int col2 = cg2 * 4 + (v2 & 3);
    const int jj2  = c32 + col2;
    const int b2   = r0 + row2;

    unsigned* flagA = g_flag + g * 32;         // phase1-done epochs, this group
    unsigned* flagB = g_flag + 256 + g * 32;   // phase2-done epochs, this group
    unsigned* myA = flagA + cid;
    unsigned* myB = flagB + cid;
    const unsigned* pairA = flagA + 2 * ks;    // 8B-aligned pair (producers of slice ks)
    const unsigned* pairB = flagB + 2 * ks;

    // staging lane map: idx = i*32+ln -> row = idx>>4, c4 = idx&15, kc = ks*16+c4
    const int strow[4] = { (0*32+ln) >> 4, (1*32+ln) >> 4, (2*32+ln) >> 4, (3*32+ln) >> 4 };
    const int stc4 = ln & 15;

    for (int t = 0; t < SEQ; ++t) {
        // prefetch gx pre-activations (DRAM; consumed ~2-3k cyc later)
        const float* gblk = g_gx + (((size_t)t * 8 + g) * 16 + cid) * 768;
        float gxzr0 = __ldcg(gblk + row1[0] * 96 + col1[0]);
        float gxzr1 = __ldcg(gblk + row1[1] * 96 + col1[1]);
        float gxc   = __ldcg(gblk + row2 * 96 + 64 + col2);

        // ---- per-warp: wait h producers, stage own k-slice (8 rows x 64) ----
        wait_pair(pairB, (unsigned)t);
        const float* hbuf = g_h + (size_t)(t & 1) * BB * HH;
#pragma unroll
        for (int i = 0; i < 4; ++i) {
            int row = strow[i];
            int kc = ks * 16 + stc4;
            float4 v = __ldcg((const float4*)(hbuf + (size_t)(r0 + row) * HH + kc * 4));
            *(float4*)&hst[row * 512 + ((kc ^ (row & 7)) << 2)] = v;
        }
        __syncwarp();

        // ---- phase1: gates GEMM, thread = 4 rows x 4 cols x 64 k ----
        {
            ull acc[4][4];
#pragma unroll
            for (int i = 0; i < 4; ++i)
#pragma unroll
                for (int j = 0; j < 4; ++j) acc[i][j] = 0ULL;

            const int kc0 = ks * 16;
#pragma unroll 4
            for (int tt = 0; tt < 16; ++tt) {
                int kc = kc0 + tt;
                ulonglong2 hv[4], wv[4];
#pragma unroll
                for (int i = 0; i < 4; ++i) {
                    int row = rg * 4 + i;
                    hv[i] = *(const ulonglong2*)&hst[row * 512 + ((kc ^ (row & 7)) << 2)];
                }
#pragma unroll
                for (int j = 0; j < 4; ++j) {
                    int col = cg * 4 + j;
                    wv[j] = *(const ulonglong2*)&wg[col * 512 + ((kc ^ (cg & 7)) << 2)];
                }
#pragma unroll
                for (int i = 0; i < 4; ++i)
#pragma unroll
                    for (int j = 0; j < 4; ++j) {
                        acc[i][j] = ffma2(hv[i].x, wv[j].x, acc[i][j]);
                        acc[i][j] = ffma2(hv[i].y, wv[j].y, acc[i][j]);
                    }
            }
#pragma unroll
            for (int i = 0; i < 4; ++i)
#pragma unroll
                for (int j = 0; j < 4; ++j)
                    P[(ks * 16 + i * 4 + j) * 32 + ln] = ull_sum(acc[i][j]);
        }
        __syncthreads();

        // ---- phase1 reduce + epilogue (z local, rh -> global) ----
#pragma unroll
        for (int vv = 0; vv < 2; ++vv) {
            int v = ks + 8 * vv;
            float s = 0.f;
#pragma unroll
            for (int q = 0; q < 8; ++q) s += P[(q * 16 + v) * 32 + ln];
            float tot = s + (vv ? gxzr1 : gxzr0);
            float sg = sigmoidf_(tot);
            int row = row1[vv], col = col1[vv];
            if (col < 32) {
                zb[row * 32 + col] = sg;
            } else {
                int jj = c32 + (col - 32);
                float hv = hst[row * 512 + (((jj >> 2) ^ (row & 7)) << 2) + (jj & 3)];
                __stcg(g_rh + (size_t)(r0 + row) * HH + jj, sg * hv);
            }
        }
        // save own h_prev before hst is overwritten by rh
        float hprev = hst[row2 * 512 + (((jj2 >> 2) ^ (row2 & 7)) << 2) + (jj2 & 3)];
        __syncthreads();                 // all hst reads + rh stores done
        if (tid == 0) flag_set(myA, (unsigned)(t + 1));

        // ---- per-warp: wait rh producers, stage own k-slice into hst ----
        wait_pair(pairA, (unsigned)(t + 1));
#pragma unroll
        for (int i = 0; i < 4; ++i) {
            int row = strow[i];
            int kc = ks * 16 + stc4;
            float4 v = __ldcg((const float4*)(g_rh + (size_t)(r0 + row) * HH + kc * 4));
            *(float4*)&hst[row * 512 + ((kc ^ (row & 7)) << 2)] = v;
        }
        __syncwarp();

        // ---- phase2: candidate GEMM, thread = 2 rows x 4 cols x 64 k ----
        {
            ull acc2[2][4];
#pragma unroll
            for (int i = 0; i < 2; ++i)
#pragma unroll
                for (int j = 0; j < 4; ++j) acc2[i][j] = 0ULL;

            const int kc0 = ks * 16;
#pragma unroll 4
            for (int tt = 0; tt < 16; ++tt) {
                int kc = kc0 + tt;
                ulonglong2 hv[2], wv[4];
#pragma unroll
                for (int i = 0; i < 2; ++i) {
                    int row = rg2 * 2 + i;
                    hv[i] = *(const ulonglong2*)&hst[row * 512 + ((kc ^ (row & 7)) << 2)];
                }
#pragma unroll
                for (int j = 0; j < 4; ++j) {
                    int col = cg2 * 4 + j;
                    wv[j] = *(const ulonglong2*)&wc[col * 512 + ((kc ^ (cg2 & 7)) << 2)];
                }
#pragma unroll
                for (int i = 0; i < 2; ++i)
#pragma unroll
                    for (int j = 0; j < 4; ++j) {
                        acc2[i][j] = ffma2(hv[i].x, wv[j].x, acc2[i][j]);
                        acc2[i][j] = ffma2(hv[i].y, wv[j].y, acc2[i][j]);
                    }
            }
#pragma unroll
            for (int i = 0; i < 2; ++i)
#pragma unroll
                for (int j = 0; j < 4; ++j)
                    P[(ks * 8 + i * 4 + j) * 32 + ln] = ull_sum(acc2[i][j]);
        }
        __syncthreads();

        // ---- phase2 reduce + h update (write ping-pong buffer) ----
        {
            float s = 0.f;
#pragma unroll
            for (int q = 0; q < 8; ++q) s += P[(q * 8 + v2) * 32 + ln];
            float cand = tanhf_(s + gxc);
            float z = zb[row2 * 32 + col2];
            float hn = fmaf(z, cand - hprev, hprev);   // (1-z)*h + z*cand
            float* hout = g_h + (size_t)((t + 1) & 1) * BB * HH;
            __stcg(hout + (size_t)b2 * HH + jj2, hn);
            if (write_outputs)
                out[((size_t)t * BB + b2) * HH + jj2] = hn;
            if (write_hlast && t == SEQ - 1) {
                size_t off = write_outputs ? (size_t)SEQ * BB * HH : 0;
                out[off + (size_t)b2 * HH + jj2] = hn;
            }
        }
        __syncthreads();                 // all P/zb reads done before next step
        if (tid == 0) flag_set(myB, (unsigned)(t + 1));
    }
}

// ---------------- launch ----------------
extern "C" void kernel_launch(void* const* d_in, const int* in_sizes, int n_in,
                              void* d_out, int out_size) {
    const float* x  = (const float*)d_in[0];
    const float* h0 = (const float*)d_in[1];
    const float* Wg = (const float*)d_in[2];
    const float* bg = (const float*)d_in[3];
    const float* Wc = (const float*)d_in[4];
    const float* bc = (const float*)d_in[5];
    float* out = (float*)d_out;

    cudaFuncSetAttribute(scan_kernel, cudaFuncAttributeMaxDynamicSharedMemorySize,
                         SMEM_BYTES);

    long long full = (long long)SEQ * BB * HH;
    int write_outputs = (out_size >= full) ? 1 : 0;
    long long hlast_off = write_outputs ? full : 0;
    int write_hlast = (out_size >= hlast_off + BB * HH) ? 1 : 0;

    dim3 pgrid(12, 1024);
    precompute_kernel<<<pgrid, NTHR>>>(x, Wg, bg, Wc, bc, h0);
    scan_kernel<<<NCTA, NTHR, SMEM_BYTES>>>(Wg, Wc, out, write_outputs, write_hlast);
}

// round 9
// speedup vs baseline: 1.6647x; 1.6647x over previous
#include <cuda_runtime.h>

#define SEQ 2048
#define BB  64
#define IND 512
#define HH  512
#define NCTA 128
#define NTHR 256

typedef unsigned long long ull;

// ---------------- global scratch (static device memory: allowed) ----------------
// gx layout: [t][group(8)][cta(16)] blocks of 8 rows x 96 cols
// (cols 0-31 z-pre, 32-63 r-pre, 64-95 cand-pre), biases folded. Block = 768 floats.
__device__ float g_gx[(size_t)SEQ * 8 * 16 * 768];
__device__ float g_h[BB * HH];        // current hidden state
__device__ float g_rh[BB * HH];       // r * h_prev
__device__ unsigned g_ctr[16 * 32];   // 16 barrier counters, padded to 128B lines

// ---------------- helpers ----------------
__device__ __forceinline__ ull ffma2(ull a, ull b, ull c) {
    ull d;
    asm("fma.rn.f32x2 %0, %1, %2, %3;" : "=l"(d) : "l"(a), "l"(b), "l"(c));
    return d;
}
__device__ __forceinline__ float ull_sum(ull v) {
    return __uint_as_float((unsigned)(v & 0xffffffffULL)) +
           __uint_as_float((unsigned)(v >> 32));
}
__device__ __forceinline__ float sigmoidf_(float x) {
    return 1.0f / (1.0f + __expf(-x));
}
__device__ __forceinline__ float tanhf_(float x) {
    return 1.0f - 2.0f / (__expf(2.0f * x) + 1.0f);
}
__device__ __forceinline__ void bar_arrive(unsigned* ctr) {
    __syncthreads();
    if (threadIdx.x == 0)
        asm volatile("red.release.gpu.global.add.u32 [%0], %1;"
                     :: "l"(ctr), "r"(1u) : "memory");
}
// Tight poll, no nanosleep: only thread 0 of each CTA polls (128 pollers
// chip-wide), so L2 traffic is negligible and wake latency is one L2 round trip.
__device__ __forceinline__ void bar_wait(unsigned* ctr, unsigned goal) {
    if (threadIdx.x == 0) {
        unsigned v;
        do {
            asm volatile("ld.acquire.gpu.u32 %0, [%1];" : "=r"(v) : "l"(ctr) : "memory");
        } while (v < goal);
    }
    __syncthreads();
}

// ---------------- precompute: gx = x @ [Wg_x | Wc_x] + [bg | bc], remapped ----
__global__ void __launch_bounds__(NTHR) precompute_kernel(
    const float* __restrict__ x, const float* __restrict__ Wg,
    const float* __restrict__ bg, const float* __restrict__ Wc,
    const float* __restrict__ bc, const float* __restrict__ h0)
{
    __shared__ float2 as2[8 * 128];
    __shared__ float2 bs2[8 * 64];

    const int tid = threadIdx.x;

    if (blockIdx.x == 0 && blockIdx.y == 0) {
        for (int i = tid; i < BB * HH; i += NTHR) g_h[i] = h0[i];
        if (tid < 16) g_ctr[tid * 32] = 0u;
    }

    const int bx = blockIdx.x;          // 0..11 (8 Wg tiles, 4 Wc tiles)
    const int m0 = blockIdx.y * 128;

    const float* Wp; const float* bias; int ldw, n0;
    if (bx < 8) { Wp = Wg; bias = bg; ldw = 1024; n0 = bx * 128; }
    else        { Wp = Wc; bias = bc; ldw = 512;  n0 = (bx - 8) * 128; }

    const int tx = tid & 15, ty = tid >> 4;
    const int arow = tid >> 1, acol = (tid & 1) * 4;
    const int bkrow = tid >> 5, bcol2 = (tid & 31) * 2;

    const float* aptr = x + (size_t)(m0 + arow) * IND + acol;
    const float* bptr = Wp + (size_t)bkrow * ldw + n0 + bcol2 * 2;

    float4 areg = *(const float4*)aptr;
    float4 breg = *(const float4*)bptr;

    ull acc[8][4];
#pragma unroll
    for (int i = 0; i < 8; ++i)
#pragma unroll
        for (int j = 0; j < 4; ++j) acc[i][j] = 0ULL;

    for (int kt = 0; kt < IND / 8; ++kt) {
        as2[(acol + 0) * 128 + arow] = make_float2(areg.x, areg.x);
        as2[(acol + 1) * 128 + arow] = make_float2(areg.y, areg.y);
        as2[(acol + 2) * 128 + arow] = make_float2(areg.z, areg.z);
        as2[(acol + 3) * 128 + arow] = make_float2(areg.w, areg.w);
        *(float4*)&bs2[bkrow * 64 + bcol2] = breg;
        __syncthreads();
        if (kt + 1 < IND / 8) {
            areg = *(const float4*)(aptr + (kt + 1) * 8);
            breg = *(const float4*)(bptr + (size_t)(kt + 1) * 8 * ldw);
        }
#pragma unroll
        for (int k = 0; k < 8; ++k) {
            ulonglong2 a01 = *(const ulonglong2*)&as2[k * 128 + ty * 8];
            ulonglong2 a23 = *(const ulonglong2*)&as2[k * 128 + ty * 8 + 2];
            ulonglong2 a45 = *(const ulonglong2*)&as2[k * 128 + ty * 8 + 4];
            ulonglong2 a67 = *(const ulonglong2*)&as2[k * 128 + ty * 8 + 6];
            ulonglong2 b01 = *(const ulonglong2*)&bs2[k * 64 + tx * 4];
            ulonglong2 b23 = *(const ulonglong2*)&bs2[k * 64 + tx * 4 + 2];
            ull av[8] = {a01.x, a01.y, a23.x, a23.y, a45.x, a45.y, a67.x, a67.y};
            ull bv[4] = {b01.x, b01.y, b23.x, b23.y};
#pragma unroll
            for (int i = 0; i < 8; ++i)
#pragma unroll
                for (int j = 0; j < 4; ++j)
                    acc[i][j] = ffma2(av[i], bv[j], acc[i][j]);
        }
        __syncthreads();
    }

    float bvl[8];
#pragma unroll
    for (int j = 0; j < 8; ++j) bvl[j] = bias[n0 + tx * 8 + j];

    // Destination remap: (bx, tx) -> (cta, slot)
    int cta, slot;
    if (bx < 8) {
        int gcol = bx * 128 + tx * 8;
        if (gcol < 512) { cta = gcol >> 5; slot = gcol & 31; }
        else { int rc = gcol - 512; cta = rc >> 5; slot = 32 + (rc & 31); }
    } else {
        int ccol = (bx - 8) * 128 + tx * 8;
        cta = ccol >> 5; slot = 64 + (ccol & 31);
    }

#pragma unroll
    for (int i = 0; i < 8; ++i) {
        int m = m0 + ty * 8 + i;
        int t = m >> 6, b = m & 63, g = b >> 3, r = b & 7;
        float* op = g_gx + (((size_t)t * 8 + g) * 16 + cta) * 768 + r * 96 + slot;
        float2 c0, c1, c2, c3;
        c0.x = __uint_as_float((unsigned)acc[i][0]); c0.y = __uint_as_float((unsigned)(acc[i][0] >> 32));
        c1.x = __uint_as_float((unsigned)acc[i][1]); c1.y = __uint_as_float((unsigned)(acc[i][1] >> 32));
        c2.x = __uint_as_float((unsigned)acc[i][2]); c2.y = __uint_as_float((unsigned)(acc[i][2] >> 32));
        c3.x = __uint_as_float((unsigned)acc[i][3]); c3.y = __uint_as_float((unsigned)(acc[i][3] >> 32));
        *(float4*)(op)     = make_float4(c0.x + bvl[0], c0.y + bvl[1],
                                         c1.x + bvl[2], c1.y + bvl[3]);
        *(float4*)(op + 4) = make_float4(c2.x + bvl[4], c2.y + bvl[5],
                                         c3.x + bvl[6], c3.y + bvl[7]);
    }
}

// ---------------- persistent scan kernel ----------------
// 128 CTAs x 256 thr, 1/SM. Group g = bid>>4 owns batch rows [g*8, g*8+8).
// cid = bid&15: z cols [cid*32,+32), r cols [512+cid*32,+32), cand cols [cid*32,+32).
// smem: wg 32768 | wc 16384 | hst 4096 (h, then rh) | P 4096 | zb 256 = 230400 B.
#define SM_WG  0
#define SM_WC  32768
#define SM_HST 49152
#define SM_P   53248
#define SM_Z   57344
#define SMEM_FLOATS 57600
#define SMEM_BYTES (SMEM_FLOATS * 4)

__global__ void __launch_bounds__(NTHR, 1) scan_kernel(
    const float* __restrict__ Wg, const float* __restrict__ Wc,
    float* __restrict__ out, int write_outputs, int write_hlast)
{
    extern __shared__ float sm[];
    float* wg  = sm + SM_WG;
    float* wc  = sm + SM_WC;
    float* hst = sm + SM_HST;
    float* P   = sm + SM_P;
    float* zb  = sm + SM_Z;

    const int tid = threadIdx.x;
    const int g   = blockIdx.x >> 4;
    const int cid = blockIdx.x & 15;
    const int r0  = g * 8;
    const int c32 = cid * 32;

    // ---- load recurrent weight slabs once (swizzled, k-contiguous per col) ----
    for (int idx = tid; idx < 64 * 512; idx += NTHR) {
        int k = idx >> 6, c = idx & 63;
        int gc = (c < 32) ? (c32 + c) : (512 + c32 + (c - 32));
        float v = Wg[(size_t)(512 + k) * 1024 + gc];
        wg[c * 512 + (((k >> 2) ^ ((c >> 2) & 7)) << 2) + (k & 3)] = v;
    }
    for (int idx = tid; idx < 32 * 512; idx += NTHR) {
        int k = idx >> 5, c = idx & 31;
        float v = Wc[(size_t)(512 + k) * 512 + c32 + c];
        wc[c * 512 + (((k >> 2) ^ ((c >> 2) & 7)) << 2) + (k & 3)] = v;
    }
    __syncthreads();

    // phase1 mapping: warp ks = k-slice (64 k), lane = (rg:2) x (cg:16), tile 4x4
    const int ks = tid >> 5;
    const int ln = tid & 31;
    const int rg = ln >> 4, cg = ln & 15;
    // phase2 mapping: lane = (rg2:4) x (cg2:8), tile 2x4
    const int rg2 = ln >> 3, cg2 = ln & 7;

    // phase1 epilogue outputs (2 per thread)
    int row1[2], col1[2];
#pragma unroll
    for (int vv = 0; vv < 2; ++vv) {
        int v = ks + 8 * vv;
        row1[vv] = rg * 4 + (v >> 2);
        col1[vv] = cg * 4 + (v & 3);
    }
    // phase2 epilogue output (1 per thread)
    const int v2   = ks;
    const int row2 = rg2 * 2 + (v2 >> 2);
    const int col2 = cg2 * 4 + (v2 & 3);
    const int jj2  = c32 + col2;
    const int b2   = r0 + row2;

    unsigned* ctrA = g_ctr + (g * 2) * 32;
    unsigned* ctrB = g_ctr + (g * 2 + 1) * 32;

    for (int t = 0; t < SEQ; ++t) {
        const float* gblk = g_gx + (((size_t)t * 8 + g) * 16 + cid) * 768;
        // prefetch gx pre-activations (DRAM; consumed ~2-3k cyc later)
        float gxzr0 = __ldcg(gblk + row1[0] * 96 + col1[0]);
        float gxzr1 = __ldcg(gblk + row1[1] * 96 + col1[1]);
        float gxc   = __ldcg(gblk + row2 * 96 + 64 + col2);

        // ---- stage h: 8 rows x 512 (16 KB), swizzled ----
#pragma unroll
        for (int it = 0; it < 4; ++it) {
            int id = tid + it * NTHR;
            int lr = id >> 7, kc = id & 127;
            float4 v = __ldcg((const float4*)(g_h + (size_t)(r0 + lr) * HH + kc * 4));
            *(float4*)&hst[lr * 512 + ((kc ^ (lr & 7)) << 2)] = v;
        }
        __syncthreads();

        // ---- phase1: gates GEMM, thread = 4 rows x 4 cols x 64 k ----
        {
            ull acc[4][4];
#pragma unroll
            for (int i = 0; i < 4; ++i)
#pragma unroll
                for (int j = 0; j < 4; ++j) acc[i][j] = 0ULL;

            const int kc0 = ks * 16;
#pragma unroll 4
            for (int tt = 0; tt < 16; ++tt) {
                int kc = kc0 + tt;
                ulonglong2 hv[4], wv[4];
#pragma unroll
                for (int i = 0; i < 4; ++i) {
                    int row = rg * 4 + i;
                    hv[i] = *(const ulonglong2*)&hst[row * 512 + ((kc ^ (row & 7)) << 2)];
                }
#pragma unroll
                for (int j = 0; j < 4; ++j) {
                    int col = cg * 4 + j;
                    wv[j] = *(const ulonglong2*)&wg[col * 512 + ((kc ^ (cg & 7)) << 2)];
                }
#pragma unroll
                for (int i = 0; i < 4; ++i)
#pragma unroll
                    for (int j = 0; j < 4; ++j) {
                        acc[i][j] = ffma2(hv[i].x, wv[j].x, acc[i][j]);
                        acc[i][j] = ffma2(hv[i].y, wv[j].y, acc[i][j]);
                    }
            }
#pragma unroll
            for (int i = 0; i < 4; ++i)
#pragma unroll
                for (int j = 0; j < 4; ++j)
                    P[(ks * 16 + i * 4 + j) * 32 + ln] = ull_sum(acc[i][j]);
        }
        __syncthreads();

        // ---- phase1 reduce + epilogue (z local, rh -> global) ----
#pragma unroll
        for (int vv = 0; vv < 2; ++vv) {
            int v = ks + 8 * vv;
            float s = 0.f;
#pragma unroll
            for (int q = 0; q < 8; ++q) s += P[(q * 16 + v) * 32 + ln];
            float tot = s + (vv ? gxzr1 : gxzr0);
            float sg = sigmoidf_(tot);
            int row = row1[vv], col = col1[vv];
            if (col < 32) {
                zb[row * 32 + col] = sg;
            } else {
                int jj = c32 + (col - 32);
                float hv = hst[row * 512 + (((jj >> 2) ^ (row & 7)) << 2) + (jj & 3)];
                __stcg(g_rh + (size_t)(r0 + row) * HH + jj, sg * hv);
            }
        }
        // save own h_prev for the phase2 update before hst is overwritten
        float hprev = hst[row2 * 512 + (((jj2 >> 2) ^ (row2 & 7)) << 2) + (jj2 & 3)];

        bar_arrive(ctrA);
        bar_wait(ctrA, (unsigned)(t + 1) * 16u);

        // ---- stage rh into hst (overwrite) ----
#pragma unroll
        for (int it = 0; it < 4; ++it) {
            int id = tid + it * NTHR;
            int lr = id >> 7, kc = id & 127;
            float4 v = __ldcg((const float4*)(g_rh + (size_t)(r0 + lr) * HH + kc * 4));
            *(float4*)&hst[lr * 512 + ((kc ^ (lr & 7)) << 2)] = v;
        }
        __syncthreads();

        // ---- phase2: candidate GEMM, thread = 2 rows x 4 cols x 64 k ----
        {
            ull acc2[2][4];
#pragma unroll
            for (int i = 0; i < 2; ++i)
#pragma unroll
                for (int j = 0; j < 4; ++j) acc2[i][j] = 0ULL;

            const int kc0 = ks * 16;
#pragma unroll 4
            for (int tt = 0; tt < 16; ++tt) {
                int kc = kc0 + tt;
                ulonglong2 hv[2], wv[4];
#pragma unroll
                for (int i = 0; i < 2; ++i) {
                    int row = rg2 * 2 + i;
                    hv[i] = *(const ulonglong2*)&hst[row * 512 + ((kc ^ (row & 7)) << 2)];
                }
#pragma unroll
                for (int j = 0; j < 4; ++j) {
                    int col = cg2 * 4 + j;
                    wv[j] = *(const ulonglong2*)&wc[col * 512 + ((kc ^ (cg2 & 7)) << 2)];
                }
#pragma unroll
                for (int i = 0; i < 2; ++i)
#pragma unroll
                    for (int j = 0; j < 4; ++j) {
                        acc2[i][j] = ffma2(hv[i].x, wv[j].x, acc2[i][j]);
                        acc2[i][j] = ffma2(hv[i].y, wv[j].y, acc2[i][j]);
                    }
            }
#pragma unroll
            for (int i = 0; i < 2; ++i)
#pragma unroll
                for (int j = 0; j < 4; ++j)
                    P[(ks * 8 + i * 4 + j) * 32 + ln] = ull_sum(acc2[i][j]);
        }
        __syncthreads();

        // ---- phase2 reduce + h update ----
        {
            float s = 0.f;
#pragma unroll
            for (int q = 0; q < 8; ++q) s += P[(q * 8 + v2) * 32 + ln];
            float cand = tanhf_(s + gxc);
            float z = zb[row2 * 32 + col2];
            float hn = fmaf(z, cand - hprev, hprev);   // (1-z)*h + z*cand
            __stcg(g_h + (size_t)b2 * HH + jj2, hn);
            if (write_outputs)
                out[((size_t)t * BB + b2) * HH + jj2] = hn;
            if (write_hlast && t == SEQ - 1) {
                size_t off = write_outputs ? (size_t)SEQ * BB * HH : 0;
                out[off + (size_t)b2 * HH + jj2] = hn;
            }
        }

        bar_arrive(ctrB);
        bar_wait(ctrB, (unsigned)(t + 1) * 16u);
    }
}

// ---------------- launch ----------------
extern "C" void kernel_launch(void* const* d_in, const int* in_sizes, int n_in,
                              void* d_out, int out_size) {
    const float* x  = (const float*)d_in[0];
    const float* h0 = (const float*)d_in[1];
    const float* Wg = (const float*)d_in[2];
    const float* bg = (const float*)d_in[3];
    const float* Wc = (const float*)d_in[4];
    const float* bc = (const float*)d_in[5];
    float* out = (float*)d_out;

    cudaFuncSetAttribute(scan_kernel, cudaFuncAttributeMaxDynamicSharedMemorySize,
                         SMEM_BYTES);

    long long full = (long long)SEQ * BB * HH;
    int write_outputs = (out_size >= full) ? 1 : 0;
    long long hlast_off = write_outputs ? full : 0;
    int write_hlast = (out_size >= hlast_off + BB * HH) ? 1 : 0;

    dim3 pgrid(12, 1024);
    precompute_kernel<<<pgrid, NTHR>>>(x, Wg, bg, Wc, bc, h0);
    scan_kernel<<<NCTA, NTHR, SMEM_BYTES>>>(Wg, Wc, out, write_outputs, write_hlast);
}

// round 10
// speedup vs baseline: 1.7254x; 1.0364x over previous
#include <cuda_runtime.h>

#define SEQ 2048
#define BB  64
#define IND 512
#define HH  512
#define NCTA 128
#define NTHR 256

typedef unsigned long long ull;

// ---------------- global scratch (static device memory: allowed) ----------------
// gx layout: [t][group(8)][cta(16)] blocks of 8 rows x 96 cols
// (cols 0-31 z-pre, 32-63 r-pre, 64-95 cand-pre), biases folded. Block = 768 floats.
__device__ float g_gx[(size_t)SEQ * 8 * 16 * 768];
__device__ float g_h[BB * HH];        // current hidden state
__device__ float g_rh[BB * HH];       // r * h_prev
__device__ unsigned g_ctr[16 * 32];   // 16 barrier counters, padded to 128B lines

// ---------------- helpers ----------------
__device__ __forceinline__ ull ffma2(ull a, ull b, ull c) {
    ull d;
    asm("fma.rn.f32x2 %0, %1, %2, %3;" : "=l"(d) : "l"(a), "l"(b), "l"(c));
    return d;
}
__device__ __forceinline__ float ull_sum(ull v) {
    return __uint_as_float((unsigned)(v & 0xffffffffULL)) +
           __uint_as_float((unsigned)(v >> 32));
}
__device__ __forceinline__ float sigmoidf_(float x) {
    return 1.0f / (1.0f + __expf(-x));
}
__device__ __forceinline__ float tanhf_(float x) {
    return 1.0f - 2.0f / (__expf(2.0f * x) + 1.0f);
}
__device__ __forceinline__ void bar_arrive(unsigned* ctr) {
    __syncthreads();
    if (threadIdx.x == 0)
        asm volatile("red.release.gpu.global.add.u32 [%0], %1;"
                     :: "l"(ctr), "r"(1u) : "memory");
}
__device__ __forceinline__ void bar_wait(unsigned* ctr, unsigned goal) {
    if (threadIdx.x == 0) {
        unsigned v;
        do {
            asm volatile("ld.acquire.gpu.u32 %0, [%1];" : "=r"(v) : "l"(ctr) : "memory");
        } while (v < goal);
    }
    __syncthreads();
}

// ---------------- precompute: gx = x @ [Wg_x | Wc_x] + [bg | bc], remapped ----
__global__ void __launch_bounds__(NTHR) precompute_kernel(
    const float* __restrict__ x, const float* __restrict__ Wg,
    const float* __restrict__ bg, const float* __restrict__ Wc,
    const float* __restrict__ bc, const float* __restrict__ h0)
{
    __shared__ float2 as2[8 * 128];
    __shared__ float2 bs2[8 * 64];

    const int tid = threadIdx.x;

    if (blockIdx.x == 0 && blockIdx.y == 0) {
        for (int i = tid; i < BB * HH; i += NTHR) g_h[i] = h0[i];
        if (tid < 16) g_ctr[tid * 32] = 0u;
    }

    const int bx = blockIdx.x;          // 0..11 (8 Wg tiles, 4 Wc tiles)
    const int m0 = blockIdx.y * 128;

    const float* Wp; const float* bias; int ldw, n0;
    if (bx < 8) { Wp = Wg; bias = bg; ldw = 1024; n0 = bx * 128; }
    else        { Wp = Wc; bias = bc; ldw = 512;  n0 = (bx - 8) * 128; }

    const int tx = tid & 15, ty = tid >> 4;
    const int arow = tid >> 1, acol = (tid & 1) * 4;
    const int bkrow = tid >> 5, bcol2 = (tid & 31) * 2;

    const float* aptr = x + (size_t)(m0 + arow) * IND + acol;
    const float* bptr = Wp + (size_t)bkrow * ldw + n0 + bcol2 * 2;

    float4 areg = *(const float4*)aptr;
    float4 breg = *(const float4*)bptr;

    ull acc[8][4];
#pragma unroll
    for (int i = 0; i < 8; ++i)
#pragma unroll
        for (int j = 0; j < 4; ++j) acc[i][j] = 0ULL;

    for (int kt = 0; kt < IND / 8; ++kt) {
        as2[(acol + 0) * 128 + arow] = make_float2(areg.x, areg.x);
        as2[(acol + 1) * 128 + arow] = make_float2(areg.y, areg.y);
        as2[(acol + 2) * 128 + arow] = make_float2(areg.z, areg.z);
        as2[(acol + 3) * 128 + arow] = make_float2(areg.w, areg.w);
        *(float4*)&bs2[bkrow * 64 + bcol2] = breg;
        __syncthreads();
        if (kt + 1 < IND / 8) {
            areg = *(const float4*)(aptr + (kt + 1) * 8);
            breg = *(const float4*)(bptr + (size_t)(kt + 1) * 8 * ldw);
        }
#pragma unroll
        for (int k = 0; k < 8; ++k) {
            ulonglong2 a01 = *(const ulonglong2*)&as2[k * 128 + ty * 8];
            ulonglong2 a23 = *(const ulonglong2*)&as2[k * 128 + ty * 8 + 2];
            ulonglong2 a45 = *(const ulonglong2*)&as2[k * 128 + ty * 8 + 4];
            ulonglong2 a67 = *(const ulonglong2*)&as2[k * 128 + ty * 8 + 6];
            ulonglong2 b01 = *(const ulonglong2*)&bs2[k * 64 + tx * 4];
            ulonglong2 b23 = *(const ulonglong2*)&bs2[k * 64 + tx * 4 + 2];
            ull av[8] = {a01.x, a01.y, a23.x, a23.y, a45.x, a45.y, a67.x, a67.y};
            ull bv[4] = {b01.x, b01.y, b23.x, b23.y};
#pragma unroll
            for (int i = 0; i < 8; ++i)
#pragma unroll
                for (int j = 0; j < 4; ++j)
                    acc[i][j] = ffma2(av[i], bv[j], acc[i][j]);
        }
        __syncthreads();
    }

    float bvl[8];
#pragma unroll
    for (int j = 0; j < 8; ++j) bvl[j] = bias[n0 + tx * 8 + j];

    // Destination remap: (bx, tx) -> (cta, slot)
    int cta, slot;
    if (bx < 8) {
        int gcol = bx * 128 + tx * 8;
        if (gcol < 512) { cta = gcol >> 5; slot = gcol & 31; }
        else { int rc = gcol - 512; cta = rc >> 5; slot = 32 + (rc & 31); }
    } else {
        int ccol = (bx - 8) * 128 + tx * 8;
        cta = ccol >> 5; slot = 64 + (ccol & 31);
    }

#pragma unroll
    for (int i = 0; i < 8; ++i) {
        int m = m0 + ty * 8 + i;
        int t = m >> 6, b = m & 63, g = b >> 3, r = b & 7;
        float* op = g_gx + (((size_t)t * 8 + g) * 16 + cta) * 768 + r * 96 + slot;
        float2 c0, c1, c2, c3;
        c0.x = __uint_as_float((unsigned)acc[i][0]); c0.y = __uint_as_float((unsigned)(acc[i][0] >> 32));
        c1.x = __uint_as_float((unsigned)acc[i][1]); c1.y = __uint_as_float((unsigned)(acc[i][1] >> 32));
        c2.x = __uint_as_float((unsigned)acc[i][2]); c2.y = __uint_as_float((unsigned)(acc[i][2] >> 32));
        c3.x = __uint_as_float((unsigned)acc[i][3]); c3.y = __uint_as_float((unsigned)(acc[i][3] >> 32));
        *(float4*)(op)     = make_float4(c0.x + bvl[0], c0.y + bvl[1],
                                         c1.x + bvl[2], c1.y + bvl[3]);
        *(float4*)(op + 4) = make_float4(c2.x + bvl[4], c2.y + bvl[5],
                                         c3.x + bvl[6], c3.y + bvl[7]);
    }
}

// ---------------- scan kernel building blocks ----------------
// All GEMMs: 8 rows x 32 cols x 512 k. Warp ks owns k-slice [ks*64, +64).
// Lane = (rg2 = ln>>3, cg2 = ln&7); thread tile 2 rows x 4 cols.
// Partials -> P section; reducer thread (ks,ln) sums value v2=ks across 8 warps
// giving output (row2, col2) = (rg2*2 + (ks>>2), cg2*4 + (ks&3)).
__device__ __forceinline__ void gemm8(const float* __restrict__ hb,
                                      const float* __restrict__ wb,
                                      float* __restrict__ Pout,
                                      int ks, int ln, int rg2, int cg2)
{
    ull acc[2][4];
#pragma unroll
    for (int i = 0; i < 2; ++i)
#pragma unroll
        for (int j = 0; j < 4; ++j) acc[i][j] = 0ULL;

    const int kc0 = ks * 16;
#pragma unroll 4
    for (int tt = 0; tt < 16; ++tt) {
        int kc = kc0 + tt;
        ulonglong2 hv[2], wv[4];
#pragma unroll
        for (int i = 0; i < 2; ++i) {
            int row = rg2 * 2 + i;                 // 0..7, row&7 == row
            hv[i] = *(const ulonglong2*)&hb[row * 512 + ((kc ^ row) << 2)];
        }
#pragma unroll
        for (int j = 0; j < 4; ++j) {
            int c = cg2 * 4 + j;                   // swizzle key (c>>2)&7 == cg2
            wv[j] = *(const ulonglong2*)&wb[c * 512 + ((kc ^ cg2) << 2)];
        }
#pragma unroll
        for (int i = 0; i < 2; ++i)
#pragma unroll
            for (int j = 0; j < 4; ++j) {
                acc[i][j] = ffma2(hv[i].x, wv[j].x, acc[i][j]);
                acc[i][j] = ffma2(hv[i].y, wv[j].y, acc[i][j]);
            }
    }
#pragma unroll
    for (int i = 0; i < 2; ++i)
#pragma unroll
        for (int j = 0; j < 4; ++j)
            Pout[(ks * 8 + i * 4 + j) * 32 + ln] = ull_sum(acc[i][j]);
}

// Per-warp staging: warp ks loads its own k-slice (8 rows x 64 k = 2 KB).
__device__ __forceinline__ void stage_slice(float* __restrict__ hst,
                                            const float* __restrict__ src,
                                            int r0, int ks, int ln)
{
#pragma unroll
    for (int i = 0; i < 4; ++i) {
        int idx = i * 32 + ln;                    // 0..127
        int row = idx >> 4;                       // 0..7
        int kc  = ks * 16 + (idx & 15);
        float4 v = __ldcg((const float4*)(src + (size_t)(r0 + row) * HH + kc * 4));
        *(float4*)&hst[row * 512 + ((kc ^ row) << 2)] = v;
    }
}

// ---------------- persistent scan kernel ----------------
// 128 CTAs x 256 thr, 1/SM. Group g = bid>>4 owns batch rows [g*8, +8).
// cid = bid&15: z cols [cid*32,+32), r cols [512+cid*32,+32), cand cols [cid*32,+32).
// Step: stage h -> r-GEMM -> rh out + arrive A -> z-GEMM (hides A) -> wait A
//       -> stage rh -> cand-GEMM -> h update + barrier B.
// smem (floats): wgz 32x512 | wgr 32x512 | wc 32x512 | hst 8x512 | P 2x2048
#define SM_WG  0
#define SM_WC  32768
#define SM_HST 49152
#define SM_P   53248
#define SMEM_FLOATS 57344
#define SMEM_BYTES (SMEM_FLOATS * 4)

__global__ void __launch_bounds__(NTHR, 1) scan_kernel(
    const float* __restrict__ Wg, const float* __restrict__ Wc,
    float* __restrict__ out, int write_outputs, int write_hlast)
{
    extern __shared__ float sm[];
    float* wg   = sm + SM_WG;          // cols 0-31 = z, 32-63 = r
    float* wc   = sm + SM_WC;
    float* hst  = sm + SM_HST;
    float* P_lo = sm + SM_P;
    float* P_hi = sm + SM_P + 2048;

    const int tid = threadIdx.x;
    const int g   = blockIdx.x >> 4;
    const int cid = blockIdx.x & 15;
    const int r0  = g * 8;
    const int c32 = cid * 32;

    // ---- load recurrent weight slabs once (swizzled, k-contiguous per col) ----
    for (int idx = tid; idx < 64 * 512; idx += NTHR) {
        int k = idx >> 6, c = idx & 63;
        int gc = (c < 32) ? (c32 + c) : (512 + c32 + (c - 32));
        float v = Wg[(size_t)(512 + k) * 1024 + gc];
        wg[c * 512 + (((k >> 2) ^ ((c >> 2) & 7)) << 2) + (k & 3)] = v;
    }
    for (int idx = tid; idx < 32 * 512; idx += NTHR) {
        int k = idx >> 5, c = idx & 31;
        float v = Wc[(size_t)(512 + k) * 512 + c32 + c];
        wc[c * 512 + (((k >> 2) ^ ((c >> 2) & 7)) << 2) + (k & 3)] = v;
    }
    __syncthreads();

    const int ks  = tid >> 5;
    const int ln  = tid & 31;
    const int rg2 = ln >> 3, cg2 = ln & 7;

    // this thread's output element (same for r, z, cand)
    const int row2 = rg2 * 2 + (ks >> 2);
    const int col2 = cg2 * 4 + (ks & 3);
    const int jj2  = c32 + col2;
    const int b2   = r0 + row2;

    unsigned* ctrA = g_ctr + (g * 2) * 32;
    unsigned* ctrB = g_ctr + (g * 2 + 1) * 32;

    // h_prev for this thread's element, carried in a register across steps
    float hprev = __ldcg(g_h + (size_t)b2 * HH + jj2);

    for (int t = 0; t < SEQ; ++t) {
        // prefetch pre-activations (DRAM; consumed >=1k cyc later)
        const float* gblk = g_gx + (((size_t)t * 8 + g) * 16 + cid) * 768;
        float gxz = __ldcg(gblk + row2 * 96 + col2);
        float gxr = __ldcg(gblk + row2 * 96 + 32 + col2);
        float gxc = __ldcg(gblk + row2 * 96 + 64 + col2);

        // ---- per-warp stage h slice, straight into r-GEMM ----
        stage_slice(hst, g_h, r0, ks, ln);
        __syncwarp();
        gemm8(hst, wg + 32 * 512, P_lo, ks, ln, rg2, cg2);   // r
        __syncthreads();

        // ---- r reduce + rh out ----
        {
            float s = 0.f;
#pragma unroll
            for (int q = 0; q < 8; ++q) s += P_lo[(q * 8 + ks) * 32 + ln];
            float r = sigmoidf_(s + gxr);
            __stcg(g_rh + (size_t)b2 * HH + jj2, r * hprev);
        }
        bar_arrive(ctrA);

        // ---- z-GEMM overlaps barrier A propagation ----
        gemm8(hst, wg, P_hi, ks, ln, rg2, cg2);              // z
        __syncthreads();
        float z;
        {
            float s = 0.f;
#pragma unroll
            for (int q = 0; q < 8; ++q) s += P_hi[(q * 8 + ks) * 32 + ln];
            z = sigmoidf_(s + gxz);
        }

        bar_wait(ctrA, (unsigned)(t + 1) * 16u);

        // ---- per-warp stage rh slice, straight into cand-GEMM ----
        stage_slice(hst, g_rh, r0, ks, ln);
        __syncwarp();
        gemm8(hst, wc, P_lo, ks, ln, rg2, cg2);              // cand
        __syncthreads();

        // ---- cand reduce + h update ----
        {
            float s = 0.f;
#pragma unroll
            for (int q = 0; q < 8; ++q) s += P_lo[(q * 8 + ks) * 32 + ln];
            float cand = tanhf_(s + gxc);
            float hn = fmaf(z, cand - hprev, hprev);   // (1-z)*h + z*cand
            __stcg(g_h + (size_t)b2 * HH + jj2, hn);
            if (write_outputs)
                __stcs(out + ((size_t)t * BB + b2) * HH + jj2, hn);
            if (write_hlast && t == SEQ - 1) {
                size_t off = write_outputs ? (size_t)SEQ * BB * HH : 0;
                out[off + (size_t)b2 * HH + jj2] = hn;
            }
            hprev = hn;                                // carry for next step
        }

        bar_arrive(ctrB);
        bar_wait(ctrB, (unsigned)(t + 1) * 16u);
    }
}

// ---------------- launch ----------------
extern "C" void kernel_launch(void* const* d_in, const int* in_sizes, int n_in,
                              void* d_out, int out_size) {
    const float* x  = (const float*)d_in[0];
    const float* h0 = (const float*)d_in[1];
    const float* Wg = (const float*)d_in[2];
    const float* bg = (const float*)d_in[3];
    const float* Wc = (const float*)d_in[4];
    const float* bc = (const float*)d_in[5];
    float* out = (float*)d_out;

    cudaFuncSetAttribute(scan_kernel, cudaFuncAttributeMaxDynamicSharedMemorySize,
                         SMEM_BYTES);

    long long full = (long long)SEQ * BB * HH;
    int write_outputs = (out_size >= full) ? 1 : 0;
    long long hlast_off = write_outputs ? full : 0;
    int write_hlast = (out_size >= hlast_off + BB * HH) ? 1 : 0;

    dim3 pgrid(12, 1024);
    precompute_kernel<<<pgrid, NTHR>>>(x, Wg, bg, Wc, bc, h0);
    scan_kernel<<<NCTA, NTHR, SMEM_BYTES>>>(Wg, Wc, out, write_outputs, write_hlast);
}